// round 13
// baseline (speedup 1.0000x reference)
#include <cuda_runtime.h>
#include <cuda_fp16.h>

#define N_NODES 50000
#define F 64
#define HDIM 128          // output cols of the dual GEMM (64 + 64)
#define BSTRIDE 128       // bucket region per node (4 reps x 32 cap)
#define BCAP 32
#define NREP 4

// Scratch: __device__ globals (allocation-free, graph-capturable).
// Invariant: g_cursor all-zero at kernel_launch entry (zero at module load;
// agg_gemm_kernel re-zeroes after reading, every run).
__device__ __align__(16) __half g_xh[(size_t)N_NODES * F];   // x in fp16
__device__ __align__(16) __half g_wt[HDIM * F];              // Wt[c][k] fp16 (n-major)
__device__ float g_dinv[N_NODES];
__device__ float g_invdeg[N_NODES];
__device__ __align__(16) int g_cursor[NREP * N_NODES];       // per (node, rep)
__device__ int g_srcsorted[(size_t)N_NODES * BSTRIDE];       // bucketed src ids

// ---------------------------------------------------------------------------
// Fused: blocks [0, nScatter) bucket-scatter edges; blocks [nScatter, ...)
// convert x -> fp16 and W -> fp16 n-major. (R11-identical, measured.)
// ---------------------------------------------------------------------------
__global__ void __launch_bounds__(256) scatter_prep_kernel(
    const int* __restrict__ ei, int E, int nScatter,
    const float* __restrict__ x,
    const float* __restrict__ W1,
    const float* __restrict__ W2) {

    if ((int)blockIdx.x < nScatter) {
        int t = blockIdx.x * 256 + threadIdx.x;
        int rep = t & (NREP - 1);
        int base = t * 4;
        if (base + 4 <= E) {
            int4 s = *(const int4*)(ei + base);
            int4 d = *(const int4*)(ei + E + base);
            int p0 = atomicAdd(&g_cursor[d.x * NREP + rep], 1);
            int p1 = atomicAdd(&g_cursor[d.y * NREP + rep], 1);
            int p2 = atomicAdd(&g_cursor[d.z * NREP + rep], 1);
            int p3 = atomicAdd(&g_cursor[d.w * NREP + rep], 1);
            g_srcsorted[(size_t)d.x * BSTRIDE + rep * BCAP + p0] = s.x;
            g_srcsorted[(size_t)d.y * BSTRIDE + rep * BCAP + p1] = s.y;
            g_srcsorted[(size_t)d.z * BSTRIDE + rep * BCAP + p2] = s.z;
            g_srcsorted[(size_t)d.w * BSTRIDE + rep * BCAP + p3] = s.w;
        } else {
            for (int e = base; e < E; e++) {
                int d = ei[E + e];
                int pos = atomicAdd(&g_cursor[d * NREP + rep], 1);
                g_srcsorted[(size_t)d * BSTRIDE + rep * BCAP + pos] = ei[e];
            }
        }
        return;
    }

    int p = (blockIdx.x - nScatter) * 256 + threadIdx.x;
    if (p < N_NODES * F / 4) {
        float4 v = *(const float4*)(x + (size_t)p * 4);
        __half2 h0 = __floats2half2_rn(v.x, v.y);
        __half2 h1 = __floats2half2_rn(v.z, v.w);
        uint2 o = make_uint2(*reinterpret_cast<unsigned*>(&h0),
                             *reinterpret_cast<unsigned*>(&h1));
        *(uint2*)(g_xh + (size_t)p * 4) = o;
    }
    if (p < HDIM * F) {
        int c = p >> 6, k = p & 63;
        float v = (c < 64) ? W1[k * 64 + c] : W2[k * 64 + (c - 64)];
        g_wt[c * F + k] = __float2half_rn(v);
    }
}

// ---------------------------------------------------------------------------
// deg = sum of 4 cursors + 1 (self loop) -> dinv, invdeg.
// ---------------------------------------------------------------------------
__global__ void __launch_bounds__(256) dinv_kernel() {
    int i = blockIdx.x * blockDim.x + threadIdx.x;
    if (i < N_NODES) {
        int4 c = *(const int4*)(g_cursor + i * NREP);
        float dg = (float)(c.x + c.y + c.z + c.w + 1);
        g_invdeg[i] = 1.0f / dg;
        g_dinv[i]   = rsqrtf(dg);
    }
}

// ---------------------------------------------------------------------------
// Fused aggregation + dual-GEMM + epilogue. Block = 128 nodes, 8 warps.
// Warp w owns rows w*16..w*16+15 of the tile (exactly the rows its MMA
// A-fragments touch). Per warp: 8 iterations of the R11 2-nodes-per-warp
// aggregation, writing fp16 a directly into the xs smem tile; then MMAs +
// register-local relu*sigmoid epilogue. Only sync: one __syncthreads for ws.
// Re-zeroes cursors after reading (restores the entry invariant).
// ---------------------------------------------------------------------------
__global__ void __launch_bounds__(256) agg_gemm_kernel(float* __restrict__ out) {
    __shared__ __half xs[128][72];   // aggregated a, fp16 (per-warp rows)
    __shared__ __half ws[128][72];   // Wt tile

    int tid = threadIdx.x;
    int row0 = blockIdx.x * 128;

    // cooperative ws load (consumed by all warps after the syncthreads)
    for (int i = tid; i < 128 * 8; i += 256) {
        int r = i >> 3, ch = i & 7;
        *(uint4*)&ws[r][ch * 8] = *(const uint4*)(g_wt + r * F + ch * 8);
    }

    int warp = tid >> 5, lane = tid & 31;
    int half = lane >> 4;          // 0 or 1
    int hl   = lane & 15;          // lane within half

    // ---- aggregation: 8 iters x 2 nodes = this warp's 16 rows ----
    #pragma unroll 1
    for (int iter = 0; iter < 8; iter++) {
        int lrow = warp * 16 + iter * 2 + half;
        int node = row0 + lrow;
        bool valid = (node < N_NODES);

        float di = 0.0f, inv = 0.0f;
        int cnt_arr[4] = {0, 0, 0, 0};
        if (valid) {
            di  = g_dinv[node];
            inv = g_invdeg[node];
            int4 cc = *(const int4*)(g_cursor + node * NREP);
            if (hl == 0)
                *(int4*)(g_cursor + node * NREP) = make_int4(0, 0, 0, 0);
            cnt_arr[0] = cc.x; cnt_arr[1] = cc.y; cnt_arr[2] = cc.z; cnt_arr[3] = cc.w;
        }

        // self-loop term
        float ax = 0.f, ay = 0.f, az = 0.f, aw = 0.f;
        if (valid) {
            uint2 u = *((const uint2*)(g_xh + (size_t)node * F) + hl);
            float2 f0 = __half22float2(*reinterpret_cast<__half2*>(&u.x));
            float2 f1 = __half22float2(*reinterpret_cast<__half2*>(&u.y));
            float self = di * di;
            ax = self * f0.x; ay = self * f0.y; az = self * f1.x; aw = self * f1.y;
        }

        #pragma unroll 1
        for (int rep = 0; rep < NREP; rep++) {
            int cnt = cnt_arr[rep];
            const int* src = g_srcsorted +
                (size_t)(valid ? node : 0) * BSTRIDE + rep * BCAP;

            int   s_lo = 0; float n_lo = 0.0f;
            if (hl < cnt)      { s_lo = src[hl];      n_lo = di * g_dinv[s_lo]; }
            int   s_hi = 0; float n_hi = 0.0f;
            if (hl + 16 < cnt) { s_hi = src[hl + 16]; n_hi = di * g_dinv[s_hi]; }

            int nsub = (cnt + 7) >> 3;
            int nsub_other = __shfl_xor_sync(0xffffffffu, nsub, 16);
            int nsub_max = max(nsub, nsub_other);

            int selbase = half << 4;
            for (int sub = 0; sub < nsub_max; sub++) {
                int   sv = (sub < 2) ? s_lo : s_hi;
                float nv = (sub < 2) ? n_lo : n_hi;
                int   off = selbase + (sub & 1) * 8;
                #pragma unroll
                for (int u2 = 0; u2 < 8; u2++) {
                    int   ss = __shfl_sync(0xffffffffu, sv, off + u2);
                    float nn = __shfl_sync(0xffffffffu, nv, off + u2);
                    uint2 v = *((const uint2*)(g_xh + (size_t)ss * F) + hl);
                    float2 f0 = __half22float2(*reinterpret_cast<__half2*>(&v.x));
                    float2 f1 = __half22float2(*reinterpret_cast<__half2*>(&v.y));
                    ax = fmaf(nn, f0.x, ax);
                    ay = fmaf(nn, f0.y, ay);
                    az = fmaf(nn, f1.x, az);
                    aw = fmaf(nn, f1.y, aw);
                }
            }
        }

        __half2 h0 = __floats2half2_rn(ax * inv, ay * inv);
        __half2 h1 = __floats2half2_rn(az * inv, aw * inv);
        uint2 o = make_uint2(*reinterpret_cast<unsigned*>(&h0),
                             *reinterpret_cast<unsigned*>(&h1));
        *(uint2*)&xs[lrow][hl * 4] = o;   // invalid rows get zeros
    }

    __syncthreads();   // ws visible to all; xs rows are own-warp anyway

    // ---- MMA + epilogue (R12-style nt loop, low register pressure) ----
    int g = lane >> 2, t = lane & 3;
    int wrow = warp * 16;

    unsigned afr[4][4];
    #pragma unroll
    for (int ks = 0; ks < 4; ks++) {
        int kb = ks * 16;
        afr[ks][0] = *(const unsigned*)&xs[wrow + g][kb + 2 * t];
        afr[ks][1] = *(const unsigned*)&xs[wrow + g + 8][kb + 2 * t];
        afr[ks][2] = *(const unsigned*)&xs[wrow + g][kb + 2 * t + 8];
        afr[ks][3] = *(const unsigned*)&xs[wrow + g + 8][kb + 2 * t + 8];
    }

    int r1 = row0 + wrow + g;
    int r2 = r1 + 8;

    #pragma unroll
    for (int nt = 0; nt < 8; nt++) {
        float c1[4] = {0.f, 0.f, 0.f, 0.f};   // layer1 (cols nt*8..)
        float c2[4] = {0.f, 0.f, 0.f, 0.f};   // layer2 (cols 64+nt*8..)
        #pragma unroll
        for (int ks = 0; ks < 4; ks++) {
            int kb = ks * 16;
            unsigned b0 = *(const unsigned*)&ws[nt * 8 + g][kb + 2 * t];
            unsigned b1 = *(const unsigned*)&ws[nt * 8 + g][kb + 2 * t + 8];
            asm volatile(
                "mma.sync.aligned.m16n8k16.row.col.f32.f16.f16.f32 "
                "{%0,%1,%2,%3}, {%4,%5,%6,%7}, {%8,%9}, {%0,%1,%2,%3};"
                : "+f"(c1[0]), "+f"(c1[1]), "+f"(c1[2]), "+f"(c1[3])
                : "r"(afr[ks][0]), "r"(afr[ks][1]), "r"(afr[ks][2]), "r"(afr[ks][3]),
                  "r"(b0), "r"(b1));
            unsigned d0 = *(const unsigned*)&ws[(nt + 8) * 8 + g][kb + 2 * t];
            unsigned d1 = *(const unsigned*)&ws[(nt + 8) * 8 + g][kb + 2 * t + 8];
            asm volatile(
                "mma.sync.aligned.m16n8k16.row.col.f32.f16.f16.f32 "
                "{%0,%1,%2,%3}, {%4,%5,%6,%7}, {%8,%9}, {%0,%1,%2,%3};"
                : "+f"(c2[0]), "+f"(c2[1]), "+f"(c2[2]), "+f"(c2[3])
                : "r"(afr[ks][0]), "r"(afr[ks][1]), "r"(afr[ks][2]), "r"(afr[ks][3]),
                  "r"(d0), "r"(d1));
        }

        int col = nt * 8 + 2 * t;
        if (r1 < N_NODES) {
            float2 o;
            o.x = fmaxf(c1[0], 0.0f) * (1.0f / (1.0f + expf(-c2[0])));
            o.y = fmaxf(c1[1], 0.0f) * (1.0f / (1.0f + expf(-c2[1])));
            *(float2*)(out + (size_t)r1 * F + col) = o;
        }
        if (r2 < N_NODES) {
            float2 o;
            o.x = fmaxf(c1[2], 0.0f) * (1.0f / (1.0f + expf(-c2[2])));
            o.y = fmaxf(c1[3], 0.0f) * (1.0f / (1.0f + expf(-c2[3])));
            *(float2*)(out + (size_t)r2 * F + col) = o;
        }
    }
}

// ---------------------------------------------------------------------------
extern "C" void kernel_launch(void* const* d_in, const int* in_sizes, int n_in,
                              void* d_out, int out_size) {
    const float* x  = (const float*)d_in[0];
    const int*   ei = (const int*)d_in[1];   // int32 (JAX x64 disabled)
    const float* W1 = (const float*)d_in[2];
    const float* W2 = (const float*)d_in[3];
    float* out = (float*)d_out;

    int E  = in_sizes[1] / 2;
    int T4 = (E + 3) / 4;
    int S  = (T4 + 255) / 256;                       // scatter blocks (first)
    int P  = (N_NODES * F / 4 + 255) / 256;          // prep blocks

    scatter_prep_kernel<<<S + P, 256>>>(ei, E, S, x, W1, W2);
    dinv_kernel<<<(N_NODES + 255) / 256, 256>>>();
    agg_gemm_kernel<<<(N_NODES + 127) / 128, 256>>>(out);
}

// round 14
// speedup vs baseline: 1.3866x; 1.3866x over previous
#include <cuda_runtime.h>
#include <cuda_fp16.h>

#define N_NODES 50000
#define F 64
#define HDIM 128          // output cols of the dual GEMM (64 + 64)
#define BSTRIDE 128       // bucket region per node (4 reps x 32 cap)
#define BCAP 32
#define NREP 4

// Scratch: __device__ globals (allocation-free, graph-capturable).
// Invariants: g_cursor all-zero at kernel_launch entry (zero at module load;
// aggx_kernel re-zeroes after reading, every run). g_y row N_NODES is a
// dummy all-zero row (never written) used by padded lanes.
__device__ __align__(16) __half g_y[(size_t)(N_NODES + 1) * F]; // dinv[n]*x[n], fp16
__device__ __align__(16) __half g_a[(size_t)N_NODES * F];       // aggregated, fp16
__device__ __align__(16) __half g_wt[HDIM * F];                 // Wt[c][k] fp16 (n-major)
__device__ float g_dinv[N_NODES];
__device__ float g_invdeg[N_NODES];
__device__ __align__(16) int g_cursor[NREP * N_NODES];          // per (node, rep)
__device__ unsigned short g_srcs[(size_t)N_NODES * BSTRIDE];    // bucketed src ids (u16)

// ---------------------------------------------------------------------------
// Fused: blocks [0, nScatter) bucket-scatter edges (u16 payload); remaining
// blocks convert W -> fp16 n-major (tiny, independent).
// ---------------------------------------------------------------------------
__global__ void __launch_bounds__(256) scatter_wt_kernel(
    const int* __restrict__ ei, int E, int nScatter,
    const float* __restrict__ W1,
    const float* __restrict__ W2) {

    if ((int)blockIdx.x < nScatter) {
        int t = blockIdx.x * 256 + threadIdx.x;
        int rep = t & (NREP - 1);
        int base = t * 4;
        if (base + 4 <= E) {
            int4 s = *(const int4*)(ei + base);
            int4 d = *(const int4*)(ei + E + base);
            int p0 = atomicAdd(&g_cursor[d.x * NREP + rep], 1);
            int p1 = atomicAdd(&g_cursor[d.y * NREP + rep], 1);
            int p2 = atomicAdd(&g_cursor[d.z * NREP + rep], 1);
            int p3 = atomicAdd(&g_cursor[d.w * NREP + rep], 1);
            g_srcs[(size_t)d.x * BSTRIDE + rep * BCAP + p0] = (unsigned short)s.x;
            g_srcs[(size_t)d.y * BSTRIDE + rep * BCAP + p1] = (unsigned short)s.y;
            g_srcs[(size_t)d.z * BSTRIDE + rep * BCAP + p2] = (unsigned short)s.z;
            g_srcs[(size_t)d.w * BSTRIDE + rep * BCAP + p3] = (unsigned short)s.w;
        } else {
            for (int e = base; e < E; e++) {
                int d = ei[E + e];
                int pos = atomicAdd(&g_cursor[d * NREP + rep], 1);
                g_srcs[(size_t)d * BSTRIDE + rep * BCAP + pos] = (unsigned short)ei[e];
            }
        }
        return;
    }

    int p = (blockIdx.x - nScatter) * 256 + threadIdx.x;
    if (p < HDIM * F) {
        int c = p >> 6, k = p & 63;
        float v = (c < 64) ? W1[k * 64 + c] : W2[k * 64 + (c - 64)];
        g_wt[c * F + k] = __float2half_rn(v);
    }
}

// ---------------------------------------------------------------------------
// dinv + prescale: one warp per 2 nodes (half-warp per node).
// Lane 0/16 of each half computes deg -> dinv/invdeg (stored), broadcasts di;
// then the half-warp loads the node's x row (float4 x 16 lanes = 256B,
// coalesced), scales by di, stores y = di*x as fp16 (single f32->f16 round).
// ---------------------------------------------------------------------------
__global__ void __launch_bounds__(256) dinv_y_kernel(const float* __restrict__ x) {
    int w    = (blockIdx.x * blockDim.x + threadIdx.x) >> 5;
    int lane = threadIdx.x & 31;
    int half = lane >> 4;
    int hl   = lane & 15;
    int node = w * 2 + half;
    if (node >= N_NODES) return;   // N_NODES even: warp-uniform exit

    float di;
    if (hl == 0) {
        int4 c = *(const int4*)(g_cursor + node * NREP);
        float dg = (float)(c.x + c.y + c.z + c.w + 1);   // +1 self loop
        di = rsqrtf(dg);
        g_dinv[node]   = di;
        g_invdeg[node] = 1.0f / dg;
    }
    di = __shfl_sync(0xffffffffu, di, half << 4);

    float4 v = *((const float4*)(x + (size_t)node * F) + hl);
    __half2 h0 = __floats2half2_rn(di * v.x, di * v.y);
    __half2 h1 = __floats2half2_rn(di * v.z, di * v.w);
    uint2 o = make_uint2(*reinterpret_cast<unsigned*>(&h0),
                         *reinterpret_cast<unsigned*>(&h1));
    *((uint2*)(g_y + (size_t)node * F) + hl) = o;
}

// ---------------------------------------------------------------------------
// Aggregate y: a[d] = dinv_d * (y_d + sum_src y_src) * invdeg_d.
// TWO nodes per warp (R11-proven structure): lanes 0-15 -> node 2w, lanes
// 16-31 -> node 2w+1; lane owns 4 cols (uint2 = 8B; 16 x 8B = one 128B row).
// No per-edge norm: padded lanes point at the zero dummy row y[N_NODES].
// Re-zeroes cursors after reading (restores the entry invariant).
// ---------------------------------------------------------------------------
__global__ void __launch_bounds__(256) aggx_kernel() {
    int w    = (blockIdx.x * blockDim.x + threadIdx.x) >> 5;
    int lane = threadIdx.x & 31;
    int half = lane >> 4;
    int hl   = lane & 15;
    int node = w * 2 + half;
    if (node >= N_NODES) return;

    float di  = g_dinv[node];
    float inv = g_invdeg[node];
    int4 cc = *(const int4*)(g_cursor + node * NREP);
    if (hl == 0)
        *(int4*)(g_cursor + node * NREP) = make_int4(0, 0, 0, 0);
    int cnt_arr[4] = {cc.x, cc.y, cc.z, cc.w};

    // self-loop: y_node with coefficient 1
    float ax, ay, az, aw;
    {
        uint2 u = *((const uint2*)(g_y + (size_t)node * F) + hl);
        float2 f0 = __half22float2(*reinterpret_cast<__half2*>(&u.x));
        float2 f1 = __half22float2(*reinterpret_cast<__half2*>(&u.y));
        ax = f0.x; ay = f0.y; az = f1.x; aw = f1.y;
    }

    #pragma unroll
    for (int rep = 0; rep < NREP; rep++) {
        int cnt = cnt_arr[rep];
        const unsigned short* src = g_srcs + (size_t)node * BSTRIDE + rep * BCAP;

        int s_lo = N_NODES, s_hi = N_NODES;     // dummy zero row
        if (hl < cnt)      s_lo = src[hl];
        if (hl + 16 < cnt) s_hi = src[hl + 16];

        int nsub = (cnt + 7) >> 3;
        int nsub_other = __shfl_xor_sync(0xffffffffu, nsub, 16);
        int nsub_max = max(nsub, nsub_other);

        int selbase = half << 4;
        for (int sub = 0; sub < nsub_max; sub++) {
            int sv  = (sub < 2) ? s_lo : s_hi;
            int off = selbase + (sub & 1) * 8;
            #pragma unroll
            for (int u2 = 0; u2 < 8; u2++) {
                int ss = __shfl_sync(0xffffffffu, sv, off + u2);
                uint2 v = *((const uint2*)(g_y + (size_t)ss * F) + hl);
                float2 f0 = __half22float2(*reinterpret_cast<__half2*>(&v.x));
                float2 f1 = __half22float2(*reinterpret_cast<__half2*>(&v.y));
                ax += f0.x; ay += f0.y; az += f1.x; aw += f1.y;
            }
        }
    }

    float s = di * inv;
    __half2 h0 = __floats2half2_rn(ax * s, ay * s);
    __half2 h1 = __floats2half2_rn(az * s, aw * s);
    uint2 o = make_uint2(*reinterpret_cast<unsigned*>(&h0),
                         *reinterpret_cast<unsigned*>(&h1));
    *((uint2*)(g_a + (size_t)node * F) + hl) = o;
}

// ---------------------------------------------------------------------------
// Fused dual-GEMM + epilogue: out = relu(a@W1) * sigmoid(a@W2).
// (R11-verbatim; measured good.)
// ---------------------------------------------------------------------------
__global__ void __launch_bounds__(256) gemm_epi_kernel(float* __restrict__ out) {
    __shared__ __half xs[128][72];
    __shared__ __half ws[128][72];

    int tid = threadIdx.x;
    int row0 = blockIdx.x * 128;

    for (int i = tid; i < 128 * 8; i += 256) {
        int r = i >> 3, ch = i & 7;
        int row = row0 + r;
        uint4 v = make_uint4(0u, 0u, 0u, 0u);
        if (row < N_NODES) v = *(const uint4*)(g_a + (size_t)row * F + ch * 8);
        *(uint4*)&xs[r][ch * 8] = v;
    }
    for (int i = tid; i < 128 * 8; i += 256) {
        int r = i >> 3, ch = i & 7;
        *(uint4*)&ws[r][ch * 8] = *(const uint4*)(g_wt + r * F + ch * 8);
    }
    __syncthreads();

    int warp = tid >> 5, lane = tid & 31;
    int g = lane >> 2, t = lane & 3;
    int wrow = warp * 16;

    float c[16][4];
    #pragma unroll
    for (int nt = 0; nt < 16; nt++)
        #pragma unroll
        for (int j = 0; j < 4; j++) c[nt][j] = 0.0f;

    #pragma unroll
    for (int ks = 0; ks < 4; ks++) {
        int kb = ks * 16;
        unsigned a0 = *(const unsigned*)&xs[wrow + g][kb + 2 * t];
        unsigned a1 = *(const unsigned*)&xs[wrow + g + 8][kb + 2 * t];
        unsigned a2 = *(const unsigned*)&xs[wrow + g][kb + 2 * t + 8];
        unsigned a3 = *(const unsigned*)&xs[wrow + g + 8][kb + 2 * t + 8];
        #pragma unroll
        for (int nt = 0; nt < 16; nt++) {
            unsigned b0 = *(const unsigned*)&ws[nt * 8 + g][kb + 2 * t];
            unsigned b1 = *(const unsigned*)&ws[nt * 8 + g][kb + 2 * t + 8];
            asm volatile(
                "mma.sync.aligned.m16n8k16.row.col.f32.f16.f16.f32 "
                "{%0,%1,%2,%3}, {%4,%5,%6,%7}, {%8,%9}, {%0,%1,%2,%3};"
                : "+f"(c[nt][0]), "+f"(c[nt][1]), "+f"(c[nt][2]), "+f"(c[nt][3])
                : "r"(a0), "r"(a1), "r"(a2), "r"(a3), "r"(b0), "r"(b1));
        }
    }

    int r1 = row0 + wrow + g;
    int r2 = r1 + 8;
    #pragma unroll
    for (int nt = 0; nt < 8; nt++) {
        int col = nt * 8 + 2 * t;
        if (r1 < N_NODES) {
            float2 o;
            o.x = fmaxf(c[nt][0], 0.0f) * (1.0f / (1.0f + expf(-c[nt + 8][0])));
            o.y = fmaxf(c[nt][1], 0.0f) * (1.0f / (1.0f + expf(-c[nt + 8][1])));
            *(float2*)(out + (size_t)r1 * F + col) = o;
        }
        if (r2 < N_NODES) {
            float2 o;
            o.x = fmaxf(c[nt][2], 0.0f) * (1.0f / (1.0f + expf(-c[nt + 8][2])));
            o.y = fmaxf(c[nt][3], 0.0f) * (1.0f / (1.0f + expf(-c[nt + 8][3])));
            *(float2*)(out + (size_t)r2 * F + col) = o;
        }
    }
}

// ---------------------------------------------------------------------------
extern "C" void kernel_launch(void* const* d_in, const int* in_sizes, int n_in,
                              void* d_out, int out_size) {
    const float* x  = (const float*)d_in[0];
    const int*   ei = (const int*)d_in[1];   // int32 (JAX x64 disabled)
    const float* W1 = (const float*)d_in[2];
    const float* W2 = (const float*)d_in[3];
    float* out = (float*)d_out;

    int E  = in_sizes[1] / 2;
    int T4 = (E + 3) / 4;
    int S  = (T4 + 255) / 256;                 // scatter blocks (first)
    int Wb = (HDIM * F + 255) / 256;           // W-convert blocks

    scatter_wt_kernel<<<S + Wb, 256>>>(ei, E, S, W1, W2);
    dinv_y_kernel<<<(N_NODES / 2 * 32 + 255) / 256, 256>>>(x);
    aggx_kernel<<<(N_NODES / 2 * 32 + 255) / 256, 256>>>();   // 2 nodes per warp
    gemm_epi_kernel<<<(N_NODES + 127) / 128, 256>>>(out);
}

// round 15
// speedup vs baseline: 1.4439x; 1.0414x over previous
#include <cuda_runtime.h>
#include <cuda_fp16.h>

#define N_NODES 50000
#define F 64
#define HDIM 128          // output cols of the dual GEMM (64 + 64)
#define BSTRIDE 128       // bucket region per node (4 reps x 32 cap)
#define BCAP 32
#define NREP 4

// Scratch: __device__ globals (allocation-free, graph-capturable).
// Invariants: g_cursor all-zero at kernel_launch entry (zero at module load;
// aggx_kernel re-zeroes after reading, every run). g_y row N_NODES is a
// dummy all-zero row (never written) used by padded lanes.
__device__ __align__(16) __half g_y[(size_t)(N_NODES + 1) * F]; // dinv[n]*x[n], fp16
__device__ __align__(16) __half g_a[(size_t)N_NODES * F];       // aggregated, fp16
__device__ __align__(16) __half g_wt[HDIM * F];                 // Wt[c][k] fp16 (n-major)
__device__ float g_dinv[N_NODES];
__device__ float g_invdeg[N_NODES];
__device__ __align__(16) int g_cursor[NREP * N_NODES];          // per (node, rep)
__device__ unsigned short g_srcs[(size_t)N_NODES * BSTRIDE];    // bucketed src ids (u16)

// ---------------------------------------------------------------------------
// Fused: blocks [0, nScatter) bucket-scatter edges (u16 payload); remaining
// blocks convert W -> fp16 n-major (tiny, independent).
// ---------------------------------------------------------------------------
__global__ void __launch_bounds__(256) scatter_wt_kernel(
    const int* __restrict__ ei, int E, int nScatter,
    const float* __restrict__ W1,
    const float* __restrict__ W2) {

    if ((int)blockIdx.x < nScatter) {
        int t = blockIdx.x * 256 + threadIdx.x;
        int rep = t & (NREP - 1);
        int base = t * 4;
        if (base + 4 <= E) {
            int4 s = *(const int4*)(ei + base);
            int4 d = *(const int4*)(ei + E + base);
            int p0 = atomicAdd(&g_cursor[d.x * NREP + rep], 1);
            int p1 = atomicAdd(&g_cursor[d.y * NREP + rep], 1);
            int p2 = atomicAdd(&g_cursor[d.z * NREP + rep], 1);
            int p3 = atomicAdd(&g_cursor[d.w * NREP + rep], 1);
            g_srcs[(size_t)d.x * BSTRIDE + rep * BCAP + p0] = (unsigned short)s.x;
            g_srcs[(size_t)d.y * BSTRIDE + rep * BCAP + p1] = (unsigned short)s.y;
            g_srcs[(size_t)d.z * BSTRIDE + rep * BCAP + p2] = (unsigned short)s.z;
            g_srcs[(size_t)d.w * BSTRIDE + rep * BCAP + p3] = (unsigned short)s.w;
        } else {
            for (int e = base; e < E; e++) {
                int d = ei[E + e];
                int pos = atomicAdd(&g_cursor[d * NREP + rep], 1);
                g_srcs[(size_t)d * BSTRIDE + rep * BCAP + pos] = (unsigned short)ei[e];
            }
        }
        return;
    }

    int p = (blockIdx.x - nScatter) * 256 + threadIdx.x;
    if (p < HDIM * F) {
        int c = p >> 6, k = p & 63;
        float v = (c < 64) ? W1[k * 64 + c] : W2[k * 64 + (c - 64)];
        g_wt[c * F + k] = __float2half_rn(v);
    }
}

// ---------------------------------------------------------------------------
// dinv + prescale: one warp per 2 nodes (half-warp per node).
// ---------------------------------------------------------------------------
__global__ void __launch_bounds__(256) dinv_y_kernel(const float* __restrict__ x) {
    int w    = (blockIdx.x * blockDim.x + threadIdx.x) >> 5;
    int lane = threadIdx.x & 31;
    int half = lane >> 4;
    int hl   = lane & 15;
    int node = w * 2 + half;
    if (node >= N_NODES) return;   // N_NODES even: warp-uniform exit

    float di;
    if (hl == 0) {
        int4 c = *(const int4*)(g_cursor + node * NREP);
        float dg = (float)(c.x + c.y + c.z + c.w + 1);   // +1 self loop
        di = rsqrtf(dg);
        g_dinv[node]   = di;
        g_invdeg[node] = 1.0f / dg;
    }
    di = __shfl_sync(0xffffffffu, di, half << 4);

    float4 v = *((const float4*)(x + (size_t)node * F) + hl);
    __half2 h0 = __floats2half2_rn(di * v.x, di * v.y);
    __half2 h1 = __floats2half2_rn(di * v.z, di * v.w);
    uint2 o = make_uint2(*reinterpret_cast<unsigned*>(&h0),
                         *reinterpret_cast<unsigned*>(&h1));
    *((uint2*)(g_y + (size_t)node * F) + hl) = o;
}

// ---------------------------------------------------------------------------
// Aggregate y: a[d] = dinv_d * (y_d + sum_src y_src) * invdeg_d.
// TWO nodes per warp; lane owns 4 cols (uint2 = 8B). Inner loop accumulates
// in fp16x2 (HADD2) and flushes to fp32 every 4 edges -> ~3.25 instr/edge.
// Padded lanes point at the zero dummy row y[N_NODES].
// Re-zeroes cursors after reading (restores the entry invariant).
// ---------------------------------------------------------------------------
__global__ void __launch_bounds__(256) aggx_kernel() {
    int w    = (blockIdx.x * blockDim.x + threadIdx.x) >> 5;
    int lane = threadIdx.x & 31;
    int half = lane >> 4;
    int hl   = lane & 15;
    int node = w * 2 + half;
    if (node >= N_NODES) return;

    float di  = g_dinv[node];
    float inv = g_invdeg[node];
    int4 cc = *(const int4*)(g_cursor + node * NREP);
    if (hl == 0)
        *(int4*)(g_cursor + node * NREP) = make_int4(0, 0, 0, 0);
    int cnt_arr[4] = {cc.x, cc.y, cc.z, cc.w};

    // self-loop: y_node with coefficient 1
    float ax, ay, az, aw;
    {
        uint2 u = *((const uint2*)(g_y + (size_t)node * F) + hl);
        float2 f0 = __half22float2(*reinterpret_cast<__half2*>(&u.x));
        float2 f1 = __half22float2(*reinterpret_cast<__half2*>(&u.y));
        ax = f0.x; ay = f0.y; az = f1.x; aw = f1.y;
    }

    const __half2 z2 = __half2half2(__ushort_as_half(0));

    #pragma unroll
    for (int rep = 0; rep < NREP; rep++) {
        int cnt = cnt_arr[rep];
        const unsigned short* src = g_srcs + (size_t)node * BSTRIDE + rep * BCAP;

        int s_lo = N_NODES, s_hi = N_NODES;     // dummy zero row
        if (hl < cnt)      s_lo = src[hl];
        if (hl + 16 < cnt) s_hi = src[hl + 16];

        int nsub = (cnt + 7) >> 3;
        int nsub_other = __shfl_xor_sync(0xffffffffu, nsub, 16);
        int nsub_max = max(nsub, nsub_other);

        int selbase = half << 4;
        for (int sub = 0; sub < nsub_max; sub++) {
            int sv  = (sub < 2) ? s_lo : s_hi;
            int off = selbase + (sub & 1) * 8;
            // two groups of 4 edges, fp16x2 partials flushed to fp32
            #pragma unroll
            for (int grp = 0; grp < 2; grp++) {
                __half2 p0 = z2, p1 = z2;
                #pragma unroll
                for (int u2 = 0; u2 < 4; u2++) {
                    int ss = __shfl_sync(0xffffffffu, sv, off + grp * 4 + u2);
                    uint2 v = *((const uint2*)(g_y + (size_t)ss * F) + hl);
                    p0 = __hadd2(p0, *reinterpret_cast<__half2*>(&v.x));
                    p1 = __hadd2(p1, *reinterpret_cast<__half2*>(&v.y));
                }
                float2 f0 = __half22float2(p0);
                float2 f1 = __half22float2(p1);
                ax += f0.x; ay += f0.y; az += f1.x; aw += f1.y;
            }
        }
    }

    float s = di * inv;
    __half2 h0 = __floats2half2_rn(ax * s, ay * s);
    __half2 h1 = __floats2half2_rn(az * s, aw * s);
    uint2 o = make_uint2(*reinterpret_cast<unsigned*>(&h0),
                         *reinterpret_cast<unsigned*>(&h1));
    *((uint2*)(g_a + (size_t)node * F) + hl) = o;
}

// ---------------------------------------------------------------------------
// Fused dual-GEMM + epilogue: out = relu(a@W1) * sigmoid(a@W2).
// 64-row tiles, 8 warps: warp = (rowgroup rg 0..3, nt-half nh 0..1).
// Doubles blocks (782) -> ~42 warps/SM for latency hiding; each warp does
// 4 nt x 4 ks x 2 layers = 32 MMAs. Register-local relu*sigmoid.
// ---------------------------------------------------------------------------
__global__ void __launch_bounds__(256) gemm_epi_kernel(float* __restrict__ out) {
    __shared__ __half xs[64][72];
    __shared__ __half ws[128][72];

    int tid = threadIdx.x;
    int row0 = blockIdx.x * 64;

    for (int i = tid; i < 64 * 8; i += 256) {
        int r = i >> 3, ch = i & 7;
        int row = row0 + r;
        uint4 v = make_uint4(0u, 0u, 0u, 0u);
        if (row < N_NODES) v = *(const uint4*)(g_a + (size_t)row * F + ch * 8);
        *(uint4*)&xs[r][ch * 8] = v;
    }
    for (int i = tid; i < 128 * 8; i += 256) {
        int r = i >> 3, ch = i & 7;
        *(uint4*)&ws[r][ch * 8] = *(const uint4*)(g_wt + r * F + ch * 8);
    }
    __syncthreads();

    int warp = tid >> 5, lane = tid & 31;
    int rg = warp & 3;          // row group: rows rg*16 .. rg*16+15
    int nh = warp >> 2;         // nt half: nt = nh*4 .. nh*4+3
    int g = lane >> 2, t = lane & 3;
    int wrow = rg * 16;

    unsigned afr[4][4];
    #pragma unroll
    for (int ks = 0; ks < 4; ks++) {
        int kb = ks * 16;
        afr[ks][0] = *(const unsigned*)&xs[wrow + g][kb + 2 * t];
        afr[ks][1] = *(const unsigned*)&xs[wrow + g + 8][kb + 2 * t];
        afr[ks][2] = *(const unsigned*)&xs[wrow + g][kb + 2 * t + 8];
        afr[ks][3] = *(const unsigned*)&xs[wrow + g + 8][kb + 2 * t + 8];
    }

    int r1 = row0 + wrow + g;
    int r2 = r1 + 8;

    #pragma unroll
    for (int nt0 = 0; nt0 < 4; nt0++) {
        int nt = nh * 4 + nt0;
        float c1[4] = {0.f, 0.f, 0.f, 0.f};   // layer1 (cols nt*8..)
        float c2[4] = {0.f, 0.f, 0.f, 0.f};   // layer2 (cols 64+nt*8..)
        #pragma unroll
        for (int ks = 0; ks < 4; ks++) {
            int kb = ks * 16;
            unsigned b0 = *(const unsigned*)&ws[nt * 8 + g][kb + 2 * t];
            unsigned b1 = *(const unsigned*)&ws[nt * 8 + g][kb + 2 * t + 8];
            asm volatile(
                "mma.sync.aligned.m16n8k16.row.col.f32.f16.f16.f32 "
                "{%0,%1,%2,%3}, {%4,%5,%6,%7}, {%8,%9}, {%0,%1,%2,%3};"
                : "+f"(c1[0]), "+f"(c1[1]), "+f"(c1[2]), "+f"(c1[3])
                : "r"(afr[ks][0]), "r"(afr[ks][1]), "r"(afr[ks][2]), "r"(afr[ks][3]),
                  "r"(b0), "r"(b1));
            unsigned d0 = *(const unsigned*)&ws[(nt + 8) * 8 + g][kb + 2 * t];
            unsigned d1 = *(const unsigned*)&ws[(nt + 8) * 8 + g][kb + 2 * t + 8];
            asm volatile(
                "mma.sync.aligned.m16n8k16.row.col.f32.f16.f16.f32 "
                "{%0,%1,%2,%3}, {%4,%5,%6,%7}, {%8,%9}, {%0,%1,%2,%3};"
                : "+f"(c2[0]), "+f"(c2[1]), "+f"(c2[2]), "+f"(c2[3])
                : "r"(afr[ks][0]), "r"(afr[ks][1]), "r"(afr[ks][2]), "r"(afr[ks][3]),
                  "r"(d0), "r"(d1));
        }

        int col = nt * 8 + 2 * t;
        if (r1 < N_NODES) {
            float2 o;
            o.x = fmaxf(c1[0], 0.0f) * (1.0f / (1.0f + expf(-c2[0])));
            o.y = fmaxf(c1[1], 0.0f) * (1.0f / (1.0f + expf(-c2[1])));
            *(float2*)(out + (size_t)r1 * F + col) = o;
        }
        if (r2 < N_NODES) {
            float2 o;
            o.x = fmaxf(c1[2], 0.0f) * (1.0f / (1.0f + expf(-c2[2])));
            o.y = fmaxf(c1[3], 0.0f) * (1.0f / (1.0f + expf(-c2[3])));
            *(float2*)(out + (size_t)r2 * F + col) = o;
        }
    }
}

// ---------------------------------------------------------------------------
extern "C" void kernel_launch(void* const* d_in, const int* in_sizes, int n_in,
                              void* d_out, int out_size) {
    const float* x  = (const float*)d_in[0];
    const int*   ei = (const int*)d_in[1];   // int32 (JAX x64 disabled)
    const float* W1 = (const float*)d_in[2];
    const float* W2 = (const float*)d_in[3];
    float* out = (float*)d_out;

    int E  = in_sizes[1] / 2;
    int T4 = (E + 3) / 4;
    int S  = (T4 + 255) / 256;                 // scatter blocks (first)
    int Wb = (HDIM * F + 255) / 256;           // W-convert blocks

    scatter_wt_kernel<<<S + Wb, 256>>>(ei, E, S, W1, W2);
    dinv_y_kernel<<<(N_NODES / 2 * 32 + 255) / 256, 256>>>(x);
    aggx_kernel<<<(N_NODES / 2 * 32 + 255) / 256, 256>>>();   // 2 nodes per warp
    gemm_epi_kernel<<<(N_NODES + 63) / 64, 256>>>(out);
}

// round 16
// speedup vs baseline: 1.4863x; 1.0293x over previous
#include <cuda_runtime.h>
#include <cuda_fp16.h>

#define N_NODES 50000
#define F 64
#define HDIM 128          // output cols of the dual GEMM (64 + 64)
#define BSTRIDE 128       // bucket region per node (4 reps x 32 cap)
#define BCAP 32
#define NREP 4

// Scratch: __device__ globals (allocation-free, graph-capturable).
// Invariants: g_cursor all-zero at kernel_launch entry (zero at module load;
// aggx_kernel re-zeroes after reading, every run). g_y row N_NODES is a
// dummy all-zero row (never written) used by padded lanes.
__device__ __align__(16) __half g_y[(size_t)(N_NODES + 1) * F]; // dinv[n]*x[n], fp16
__device__ __align__(16) __half g_a[(size_t)N_NODES * F];       // aggregated, fp16
__device__ __align__(16) uint4 g_wf[8 * 4 * 32];                // W MMA fragments
__device__ float g_dinv[N_NODES];
__device__ float g_invdeg[N_NODES];
__device__ __align__(16) int g_cursor[NREP * N_NODES];          // per (node, rep)
__device__ unsigned short g_srcs[(size_t)N_NODES * BSTRIDE];    // bucketed src ids (u16)

// ---------------------------------------------------------------------------
// Fused: blocks [0, nScatter) bucket-scatter edges (u16 payload); remaining
// blocks pre-pack W into per-lane MMA fragments (1024 entries, tiny).
// Fragment (nt 0..7, ks 0..3, lane 0..31), lane = (g<<2)|t:
//   b0 = h2(W1[k0][c], W1[k0+1][c]),  b1 = same at k0+8   (c = nt*8+g, k0 = ks*16+2t)
//   d0, d1 = same from W2.  (Matches mma.m16n8k16 row.col B-fragment layout.)
// ---------------------------------------------------------------------------
__global__ void __launch_bounds__(256) scatter_wf_kernel(
    const int* __restrict__ ei, int E, int nScatter,
    const float* __restrict__ W1,
    const float* __restrict__ W2) {

    if ((int)blockIdx.x < nScatter) {
        int t = blockIdx.x * 256 + threadIdx.x;
        int rep = t & (NREP - 1);
        int base = t * 4;
        if (base + 4 <= E) {
            int4 s = *(const int4*)(ei + base);
            int4 d = *(const int4*)(ei + E + base);
            int p0 = atomicAdd(&g_cursor[d.x * NREP + rep], 1);
            int p1 = atomicAdd(&g_cursor[d.y * NREP + rep], 1);
            int p2 = atomicAdd(&g_cursor[d.z * NREP + rep], 1);
            int p3 = atomicAdd(&g_cursor[d.w * NREP + rep], 1);
            g_srcs[(size_t)d.x * BSTRIDE + rep * BCAP + p0] = (unsigned short)s.x;
            g_srcs[(size_t)d.y * BSTRIDE + rep * BCAP + p1] = (unsigned short)s.y;
            g_srcs[(size_t)d.z * BSTRIDE + rep * BCAP + p2] = (unsigned short)s.z;
            g_srcs[(size_t)d.w * BSTRIDE + rep * BCAP + p3] = (unsigned short)s.w;
        } else {
            for (int e = base; e < E; e++) {
                int d = ei[E + e];
                int pos = atomicAdd(&g_cursor[d * NREP + rep], 1);
                g_srcs[(size_t)d * BSTRIDE + rep * BCAP + pos] = (unsigned short)ei[e];
            }
        }
        return;
    }

    int p = (blockIdx.x - nScatter) * 256 + threadIdx.x;
    if (p < 8 * 4 * 32) {
        int lane = p & 31;
        int ks   = (p >> 5) & 3;
        int nt   = p >> 7;            // 0..7
        int g = lane >> 2, t = lane & 3;
        int c  = nt * 8 + g;          // W column (0..63)
        int k0 = ks * 16 + 2 * t;     // W row
        __half2 b0 = __floats2half2_rn(W1[(k0    ) * 64 + c], W1[(k0 + 1) * 64 + c]);
        __half2 b1 = __floats2half2_rn(W1[(k0 + 8) * 64 + c], W1[(k0 + 9) * 64 + c]);
        __half2 d0 = __floats2half2_rn(W2[(k0    ) * 64 + c], W2[(k0 + 1) * 64 + c]);
        __half2 d1 = __floats2half2_rn(W2[(k0 + 8) * 64 + c], W2[(k0 + 9) * 64 + c]);
        uint4 o = make_uint4(*reinterpret_cast<unsigned*>(&b0),
                             *reinterpret_cast<unsigned*>(&b1),
                             *reinterpret_cast<unsigned*>(&d0),
                             *reinterpret_cast<unsigned*>(&d1));
        g_wf[p] = o;
    }
}

// ---------------------------------------------------------------------------
// dinv + prescale: one warp per 2 nodes (half-warp per node).
// ---------------------------------------------------------------------------
__global__ void __launch_bounds__(256) dinv_y_kernel(const float* __restrict__ x) {
    int w    = (blockIdx.x * blockDim.x + threadIdx.x) >> 5;
    int lane = threadIdx.x & 31;
    int half = lane >> 4;
    int hl   = lane & 15;
    int node = w * 2 + half;
    if (node >= N_NODES) return;   // N_NODES even: warp-uniform exit

    float di;
    if (hl == 0) {
        int4 c = *(const int4*)(g_cursor + node * NREP);
        float dg = (float)(c.x + c.y + c.z + c.w + 1);   // +1 self loop
        di = rsqrtf(dg);
        g_dinv[node]   = di;
        g_invdeg[node] = 1.0f / dg;
    }
    di = __shfl_sync(0xffffffffu, di, half << 4);

    float4 v = *((const float4*)(x + (size_t)node * F) + hl);
    __half2 h0 = __floats2half2_rn(di * v.x, di * v.y);
    __half2 h1 = __floats2half2_rn(di * v.z, di * v.w);
    uint2 o = make_uint2(*reinterpret_cast<unsigned*>(&h0),
                         *reinterpret_cast<unsigned*>(&h1));
    *((uint2*)(g_y + (size_t)node * F) + hl) = o;
}

// ---------------------------------------------------------------------------
// Aggregate y (R15-verbatim): a[d] = dinv_d * (y_d + sum_src y_src) * invdeg_d.
// TWO nodes per warp; lane owns 4 cols (uint2). fp16x2 partials, 4-edge flush.
// Padded lanes point at the zero dummy row y[N_NODES].
// Re-zeroes cursors after reading (restores the entry invariant).
// ---------------------------------------------------------------------------
__global__ void __launch_bounds__(256) aggx_kernel() {
    int w    = (blockIdx.x * blockDim.x + threadIdx.x) >> 5;
    int lane = threadIdx.x & 31;
    int half = lane >> 4;
    int hl   = lane & 15;
    int node = w * 2 + half;
    if (node >= N_NODES) return;

    float di  = g_dinv[node];
    float inv = g_invdeg[node];
    int4 cc = *(const int4*)(g_cursor + node * NREP);
    if (hl == 0)
        *(int4*)(g_cursor + node * NREP) = make_int4(0, 0, 0, 0);
    int cnt_arr[4] = {cc.x, cc.y, cc.z, cc.w};

    float ax, ay, az, aw;
    {
        uint2 u = *((const uint2*)(g_y + (size_t)node * F) + hl);
        float2 f0 = __half22float2(*reinterpret_cast<__half2*>(&u.x));
        float2 f1 = __half22float2(*reinterpret_cast<__half2*>(&u.y));
        ax = f0.x; ay = f0.y; az = f1.x; aw = f1.y;
    }

    const __half2 z2 = __half2half2(__ushort_as_half(0));

    #pragma unroll
    for (int rep = 0; rep < NREP; rep++) {
        int cnt = cnt_arr[rep];
        const unsigned short* src = g_srcs + (size_t)node * BSTRIDE + rep * BCAP;

        int s_lo = N_NODES, s_hi = N_NODES;     // dummy zero row
        if (hl < cnt)      s_lo = src[hl];
        if (hl + 16 < cnt) s_hi = src[hl + 16];

        int nsub = (cnt + 7) >> 3;
        int nsub_other = __shfl_xor_sync(0xffffffffu, nsub, 16);
        int nsub_max = max(nsub, nsub_other);

        int selbase = half << 4;
        for (int sub = 0; sub < nsub_max; sub++) {
            int sv  = (sub < 2) ? s_lo : s_hi;
            int off = selbase + (sub & 1) * 8;
            #pragma unroll
            for (int grp = 0; grp < 2; grp++) {
                __half2 p0 = z2, p1 = z2;
                #pragma unroll
                for (int u2 = 0; u2 < 4; u2++) {
                    int ss = __shfl_sync(0xffffffffu, sv, off + grp * 4 + u2);
                    uint2 v = *((const uint2*)(g_y + (size_t)ss * F) + hl);
                    p0 = __hadd2(p0, *reinterpret_cast<__half2*>(&v.x));
                    p1 = __hadd2(p1, *reinterpret_cast<__half2*>(&v.y));
                }
                float2 f0 = __half22float2(p0);
                float2 f1 = __half22float2(p1);
                ax += f0.x; ay += f0.y; az += f1.x; aw += f1.y;
            }
        }
    }

    float s = di * inv;
    __half2 h0 = __floats2half2_rn(ax * s, ay * s);
    __half2 h1 = __floats2half2_rn(az * s, aw * s);
    uint2 o = make_uint2(*reinterpret_cast<unsigned*>(&h0),
                         *reinterpret_cast<unsigned*>(&h1));
    *((uint2*)(g_a + (size_t)node * F) + hl) = o;
}

// ---------------------------------------------------------------------------
// Fused dual-GEMM + epilogue, barrier-free: out = relu(a@W1)*sigmoid(a@W2).
// 64-row tiles, 8 warps: warp = (rg 0..3, nh 0..1). Each warp stages its own
// 16 A-rows into its xs[nh] slice (duplicate across nh partners; no block
// barrier, just __syncwarp). B fragments come straight from g_wf via one
// coalesced LDG.128 per (nt, ks) -> no W smem, no address math.
// ---------------------------------------------------------------------------
__global__ void __launch_bounds__(256) gemm_epi_kernel(float* __restrict__ out) {
    __shared__ __half xs[2][64][72];

    int tid  = threadIdx.x;
    int row0 = blockIdx.x * 64;
    int warp = tid >> 5, lane = tid & 31;
    int rg = warp & 3;          // row group: rows rg*16 .. rg*16+15
    int nh = warp >> 2;         // nt half: nt = nh*4 .. nh*4+3
    int wrow = rg * 16;

    // per-warp A staging: 16 rows x 8 uint4 chunks = 128, 4 per lane
    #pragma unroll
    for (int i = 0; i < 4; i++) {
        int li = lane + i * 32;
        int r  = wrow + (li >> 3);
        int ch = li & 7;
        int row = row0 + r;
        uint4 v = make_uint4(0u, 0u, 0u, 0u);
        if (row < N_NODES) v = *(const uint4*)(g_a + (size_t)row * F + ch * 8);
        *(uint4*)&xs[nh][r][ch * 8] = v;
    }
    __syncwarp();

    int g = lane >> 2, t = lane & 3;

    unsigned afr[4][4];
    #pragma unroll
    for (int ks = 0; ks < 4; ks++) {
        int kb = ks * 16;
        afr[ks][0] = *(const unsigned*)&xs[nh][wrow + g][kb + 2 * t];
        afr[ks][1] = *(const unsigned*)&xs[nh][wrow + g + 8][kb + 2 * t];
        afr[ks][2] = *(const unsigned*)&xs[nh][wrow + g][kb + 2 * t + 8];
        afr[ks][3] = *(const unsigned*)&xs[nh][wrow + g + 8][kb + 2 * t + 8];
    }

    int r1 = row0 + wrow + g;
    int r2 = r1 + 8;

    #pragma unroll
    for (int nt0 = 0; nt0 < 4; nt0++) {
        int nt = nh * 4 + nt0;
        const uint4* wf = g_wf + (nt * 4) * 32 + lane;
        float c1[4] = {0.f, 0.f, 0.f, 0.f};   // layer1 (cols nt*8..)
        float c2[4] = {0.f, 0.f, 0.f, 0.f};   // layer2 (cols 64+nt*8..)
        #pragma unroll
        for (int ks = 0; ks < 4; ks++) {
            uint4 f = wf[ks * 32];
            asm volatile(
                "mma.sync.aligned.m16n8k16.row.col.f32.f16.f16.f32 "
                "{%0,%1,%2,%3}, {%4,%5,%6,%7}, {%8,%9}, {%0,%1,%2,%3};"
                : "+f"(c1[0]), "+f"(c1[1]), "+f"(c1[2]), "+f"(c1[3])
                : "r"(afr[ks][0]), "r"(afr[ks][1]), "r"(afr[ks][2]), "r"(afr[ks][3]),
                  "r"(f.x), "r"(f.y));
            asm volatile(
                "mma.sync.aligned.m16n8k16.row.col.f32.f16.f16.f32 "
                "{%0,%1,%2,%3}, {%4,%5,%6,%7}, {%8,%9}, {%0,%1,%2,%3};"
                : "+f"(c2[0]), "+f"(c2[1]), "+f"(c2[2]), "+f"(c2[3])
                : "r"(afr[ks][0]), "r"(afr[ks][1]), "r"(afr[ks][2]), "r"(afr[ks][3]),
                  "r"(f.z), "r"(f.w));
        }

        int col = nt * 8 + 2 * t;
        if (r1 < N_NODES) {
            float2 o;
            o.x = fmaxf(c1[0], 0.0f) * __fdividef(1.0f, 1.0f + __expf(-c2[0]));
            o.y = fmaxf(c1[1], 0.0f) * __fdividef(1.0f, 1.0f + __expf(-c2[1]));
            *(float2*)(out + (size_t)r1 * F + col) = o;
        }
        if (r2 < N_NODES) {
            float2 o;
            o.x = fmaxf(c1[2], 0.0f) * __fdividef(1.0f, 1.0f + __expf(-c2[2]));
            o.y = fmaxf(c1[3], 0.0f) * __fdividef(1.0f, 1.0f + __expf(-c2[3]));
            *(float2*)(out + (size_t)r2 * F + col) = o;
        }
    }
}

// ---------------------------------------------------------------------------
extern "C" void kernel_launch(void* const* d_in, const int* in_sizes, int n_in,
                              void* d_out, int out_size) {
    const float* x  = (const float*)d_in[0];
    const int*   ei = (const int*)d_in[1];   // int32 (JAX x64 disabled)
    const float* W1 = (const float*)d_in[2];
    const float* W2 = (const float*)d_in[3];
    float* out = (float*)d_out;

    int E  = in_sizes[1] / 2;
    int T4 = (E + 3) / 4;
    int S  = (T4 + 255) / 256;                 // scatter blocks (first)
    int Wb = (8 * 4 * 32 + 255) / 256;         // W-fragment pack blocks

    scatter_wf_kernel<<<S + Wb, 256>>>(ei, E, S, W1, W2);
    dinv_y_kernel<<<(N_NODES / 2 * 32 + 255) / 256, 256>>>(x);
    aggx_kernel<<<(N_NODES / 2 * 32 + 255) / 256, 256>>>();   // 2 nodes per warp
    gemm_epi_kernel<<<(N_NODES + 63) / 64, 256>>>(out);
}